// round 9
// baseline (speedup 1.0000x reference)
#include <cuda_runtime.h>
#include <math.h>

#define Bn 8
#define Tn 512
#define Nn 64
#define Hn 8
#define Mt 64
#define PREDn 96
#define HIDn 256

#define TWO_PI 6.283185307179586
typedef unsigned long long ull;

// ---------------- f32x2 helpers ----------------
__device__ __forceinline__ ull ffma2(ull a, ull b, ull c) {
    ull d;
    asm("fma.rn.f32x2 %0, %1, %2, %3;" : "=l"(d) : "l"(a), "l"(b), "l"(c));
    return d;
}
__device__ __forceinline__ ull pack2(float x, float y) {
    ull r;
    asm("mov.b64 %0, {%1, %2};" : "=l"(r) : "f"(x), "f"(y));
    return r;
}
__device__ __forceinline__ float2 unpack2(ull v) {
    float2 r;
    asm("mov.b64 {%0, %1}, %2;" : "=f"(r.x), "=f"(r.y) : "l"(v));
    return r;
}

// ---------------- device scratch ----------------
__device__ float  d_res[Bn*Tn*Nn];
__device__ float  d_trend[Bn*Tn*Nn];
__device__ float  d_h1[512*256];
__device__ float  d_h2[512*256];
__device__ float  d_trend_out[Bn*PREDn*Nn];
__device__ float  d_G2[Bn*Tn*Nn*Hn];       // (b,t,(n,h))
__device__ float2 d_z[Bn*Nn*Mt];           // (b,n,tau)

// precomputed small params
__device__ float  d_cabs[Hn];
__device__ float  d_C[Hn][Hn][Hn];
__device__ float  d_Otil[Hn][Hn];
__device__ float2 d_TW64[64];
__device__ ull    d_TWp[512];
__device__ float  d_Cw[Mt*PREDn], d_Sw[Mt*PREDn];

// ---------------- setupA: twiddles + cabs ----------------
__global__ void k_setupA(const float* __restrict__ emb,
                         const float* __restrict__ cWq, const float* __restrict__ cWk)
{
    __shared__ float eq[128], ek[128];
    int t = threadIdx.x; // 512 threads

    if (t < 64) {
        double a = TWO_PI * (double)t / 64.0;
        d_TW64[t] = make_float2((float)cos(a), (float)sin(a));
    }
    {
        double a = TWO_PI * (double)t / 512.0;
        d_TWp[t] = pack2((float)cos(a), -(float)sin(a));
    }
    if (t < 128) {
        float aq = 0.f, ak = 0.f;
        #pragma unroll 4
        for (int d = 0; d < 128; d++) {
            float e = emb[d];
            aq = fmaf(e, cWq[d*128 + t], aq);
            ak = fmaf(e, cWk[d*128 + t], ak);
        }
        eq[t] = aq; ek[t] = ak;
    }
    __syncthreads();
    if (t < 8) {
        float c = 0.f;
        #pragma unroll
        for (int d = 0; d < 16; d++) c = fmaf(eq[t*16 + d], ek[t*16 + d], c);
        d_cabs[t] = fabsf(c);
    }
}

// ---------------- setupB: C / Otil ----------------
__global__ void k_setupB(const float* __restrict__ emb,
                         const float* __restrict__ cWv, const float* __restrict__ cWo,
                         const float* __restrict__ tWq, const float* __restrict__ tWk,
                         const float* __restrict__ tWv, const float* __restrict__ tWo,
                         const float* __restrict__ dr_w)
{
    __shared__ float ev[128], wod[128];
    __shared__ float P[8][128];
    __shared__ float Qg[8][128], Kg[8][128], Vg[8][128];
    int t = threadIdx.x; // 1024 threads

    if (t < 128) {
        float av = 0.f;
        #pragma unroll 4
        for (int d = 0; d < 128; d++) av = fmaf(emb[d], cWv[d*128 + t], av);
        ev[t] = av;
        float s = 0.f;
        #pragma unroll 4
        for (int e = 0; e < 128; e++) s = fmaf(tWo[t*128 + e], dr_w[e], s);
        wod[t] = s;
    }
    __syncthreads();

    {
        int h = t >> 7, e = t & 127;
        float s = 0.f;
        #pragma unroll
        for (int d = 0; d < 16; d++) s = fmaf(ev[h*16 + d], cWo[(h*16 + d)*128 + e], s);
        P[h][e] = s;
    }
    __syncthreads();

    {
        int h = t >> 7, e = t & 127;
        float sq = 0.f, sk = 0.f, sv = 0.f;
        #pragma unroll 4
        for (int d = 0; d < 128; d++) {
            float p = P[h][d];
            sq = fmaf(p, tWq[d*128 + e], sq);
            sk = fmaf(p, tWk[d*128 + e], sk);
            sv = fmaf(p, tWv[d*128 + e], sv);
        }
        Qg[h][e] = sq; Kg[h][e] = sk; Vg[h][e] = sv;
    }
    __syncthreads();

    if (t < 512) {
        int hp = t >> 6, h1 = (t >> 3) & 7, h2 = t & 7;
        float s = 0.f;
        #pragma unroll
        for (int d = 0; d < 16; d++) s = fmaf(Qg[h1][hp*16 + d], Kg[h2][hp*16 + d], s);
        d_C[hp][h1][h2] = s;
    }
    if (t >= 512 && t < 576) {
        int u = t - 512;
        int hp = u >> 3, h2 = u & 7;
        float s = 0.f;
        #pragma unroll
        for (int d = 0; d < 16; d++) s = fmaf(Vg[h2][hp*16 + d], wod[hp*16 + d], s);
        d_Otil[hp][h2] = s;
    }
}

// ---------------- cwsw: self-contained, off critical path ----------------
__global__ void k_setup_cwsw(const float* __restrict__ out_w)
{
    int tau = blockIdx.x, p = threadIdx.x; // 64 x 96
    float c = 0.f, s = 0.f;
    int k = 0;
    #pragma unroll 4
    for (int t = 0; t < 512; t++) {
        float w = out_w[t*PREDn + p];
        float cs, sn;
        sincospif((float)k * (1.f/256.f), &sn, &cs);
        c = fmaf(cs, w, c);
        s = fmaf(sn, w, s);
        k = (k + tau) & 511;
    }
    d_Cw[tau*PREDn + p] = c;
    d_Sw[tau*PREDn + p] = s;
}

// ---------------- decomposition (b-split) ----------------
__global__ void k_decomp(const float* __restrict__ x,
                         const float* __restrict__ dec_w, const float* __restrict__ dec_b,
                         int b0)
{
    __shared__ float xs[80][64];
    int b = blockIdx.y + b0, t0 = blockIdx.x * 32;
    int tid = threadIdx.x;
    const float* xb = x + b*Tn*Nn;

    for (int i = tid; i < 80*64; i += 512) {
        int row = i >> 6, col = i & 63;
        int tg = t0 - 24 + row;
        tg = tg < 0 ? 0 : (tg > 511 ? 511 : tg);
        xs[row][col] = xb[tg*64 + col];
    }
    __syncthreads();

    float w0 = dec_w[0], w1v = dec_w[1], bb0 = dec_b[0], bb1 = dec_b[1];
    int c = tid >> 6, n = tid & 63;
    int r0 = c * 4;
    float s49 = 0.f, s17 = 0.f;
    #pragma unroll
    for (int j = 0; j < 49; j++) {
        float v = xs[r0 + j][n];
        s49 += v;
        if (j >= 16 && j <= 32) s17 += v;
    }
    #pragma unroll
    for (int s = 0; s < 4; s++) {
        if (s > 0) {
            s49 += xs[r0 + 48 + s][n] - xs[r0 + s - 1][n];
            s17 += xs[r0 + 32 + s][n] - xs[r0 + 15 + s][n];
        }
        float xv = xs[r0 + 24 + s][n];
        float m17 = s17 * (1.f/17.f), m49 = s49 * (1.f/49.f);
        float l0 = fmaf(xv, w0, bb0);
        float l1 = fmaf(xv, w1v, bb1);
        float mx = fmaxf(l0, l1);
        float e0 = __expf(l0 - mx), e1 = __expf(l1 - mx);
        float tr = (m17*e0 + m49*e1) / (e0 + e1);
        int gi = b*Tn*Nn + (t0 + r0 + s)*64 + n;
        d_trend[gi] = tr;
        d_res[gi]   = xv - tr;
    }
}

// ---------------- MLP GEMMs (proven) ----------------
__global__ void k_gemm1(const float* __restrict__ w1, const float* __restrict__ b1)
{
    __shared__ float As[32][36];
    __shared__ float Ws[32][36];
    int r0 = blockIdx.y * 32, c0 = blockIdx.x * 32;
    int b = r0 >> 6, n0 = r0 & 32;
    int tid = threadIdx.x;
    int lr = tid >> 3, l4 = (tid & 7) * 4;
    int ty = tid >> 4, cy = tid & 15;

    float2 bias = *(const float2*)&b1[c0 + 2*cy];
    float a00 = bias.x, a01 = bias.y, a10 = bias.x, a11 = bias.y;

    float4 ra = *(const float4*)&d_trend[b*32768 + lr*64 + n0 + l4];
    float4 rw = *(const float4*)&w1[lr*256 + c0 + l4];

    for (int kt = 0; kt < 16; kt++) {
        *(float4*)&As[lr][l4] = ra;
        *(float4*)&Ws[lr][l4] = rw;
        __syncthreads();
        if (kt < 15) {
            int kg = (kt+1)*32 + lr;
            ra = *(const float4*)&d_trend[b*32768 + kg*64 + n0 + l4];
            rw = *(const float4*)&w1[kg*256 + c0 + l4];
        }
        #pragma unroll
        for (int k = 0; k < 32; k++) {
            float2 a = *(const float2*)&As[k][2*ty];
            float2 w = *(const float2*)&Ws[k][2*cy];
            a00 = fmaf(a.x, w.x, a00); a01 = fmaf(a.x, w.y, a01);
            a10 = fmaf(a.y, w.x, a10); a11 = fmaf(a.y, w.y, a11);
        }
        __syncthreads();
    }
    int r = r0 + 2*ty, cc = c0 + 2*cy;
    d_h1[(r+0)*256 + cc+0] = fmaxf(a00, 0.f);
    d_h1[(r+0)*256 + cc+1] = fmaxf(a01, 0.f);
    d_h1[(r+1)*256 + cc+0] = fmaxf(a10, 0.f);
    d_h1[(r+1)*256 + cc+1] = fmaxf(a11, 0.f);
}

__global__ void k_gemm2(const float* __restrict__ w2, const float* __restrict__ b2)
{
    __shared__ float As[32][34];
    __shared__ float Ws[32][36];
    int r0 = blockIdx.y * 32, c0 = blockIdx.x * 32;
    int tid = threadIdx.x;
    int alr = tid >> 3, al4 = (tid & 7) * 4;
    int ty = tid >> 4, cy = tid & 15;

    float2 bias = *(const float2*)&b2[c0 + 2*cy];
    float a00 = bias.x, a01 = bias.y, a10 = bias.x, a11 = bias.y;

    float4 ra = *(const float4*)&d_h1[(r0 + alr)*256 + al4];
    float4 rw = *(const float4*)&w2[alr*256 + c0 + al4];

    for (int kt = 0; kt < 8; kt++) {
        As[al4+0][alr] = ra.x; As[al4+1][alr] = ra.y;
        As[al4+2][alr] = ra.z; As[al4+3][alr] = ra.w;
        *(float4*)&Ws[alr][al4] = rw;
        __syncthreads();
        if (kt < 7) {
            ra = *(const float4*)&d_h1[(r0 + alr)*256 + (kt+1)*32 + al4];
            rw = *(const float4*)&w2[((kt+1)*32 + alr)*256 + c0 + al4];
        }
        #pragma unroll
        for (int k = 0; k < 32; k++) {
            float2 a = *(const float2*)&As[k][2*ty];
            float2 w = *(const float2*)&Ws[k][2*cy];
            a00 = fmaf(a.x, w.x, a00); a01 = fmaf(a.x, w.y, a01);
            a10 = fmaf(a.y, w.x, a10); a11 = fmaf(a.y, w.y, a11);
        }
        __syncthreads();
    }
    int r = r0 + 2*ty, cc = c0 + 2*cy;
    d_h2[(r+0)*256 + cc+0] = fmaxf(a00, 0.f);
    d_h2[(r+0)*256 + cc+1] = fmaxf(a01, 0.f);
    d_h2[(r+1)*256 + cc+0] = fmaxf(a10, 0.f);
    d_h2[(r+1)*256 + cc+1] = fmaxf(a11, 0.f);
}

__global__ void k_gemm3(const float* __restrict__ w3, const float* __restrict__ b3)
{
    __shared__ float As[32][34];
    __shared__ float Ws[32][36];
    int r0 = blockIdx.y * 32, c0 = blockIdx.x * 32;
    int tid = threadIdx.x;
    int alr = tid >> 3, al4 = (tid & 7) * 4;
    int ty = tid >> 4, cy = tid & 15;

    float2 bias = *(const float2*)&b3[c0 + 2*cy];
    float a00 = bias.x, a01 = bias.y, a10 = bias.x, a11 = bias.y;

    float4 ra = *(const float4*)&d_h2[(r0 + alr)*256 + al4];
    float4 rw = *(const float4*)&w3[alr*96 + c0 + al4];

    for (int kt = 0; kt < 8; kt++) {
        As[al4+0][alr] = ra.x; As[al4+1][alr] = ra.y;
        As[al4+2][alr] = ra.z; As[al4+3][alr] = ra.w;
        *(float4*)&Ws[alr][al4] = rw;
        __syncthreads();
        if (kt < 7) {
            ra = *(const float4*)&d_h2[(r0 + alr)*256 + (kt+1)*32 + al4];
            rw = *(const float4*)&w3[((kt+1)*32 + alr)*96 + c0 + al4];
        }
        #pragma unroll
        for (int k = 0; k < 32; k++) {
            float2 a = *(const float2*)&As[k][2*ty];
            float2 w = *(const float2*)&Ws[k][2*cy];
            a00 = fmaf(a.x, w.x, a00); a01 = fmaf(a.x, w.y, a01);
            a10 = fmaf(a.y, w.x, a10); a11 = fmaf(a.y, w.y, a11);
        }
        __syncthreads();
    }
    int r = r0 + 2*ty, cc = c0 + 2*cy;
    int b = r >> 6, n = r & 63;
    d_trend_out[(b*PREDn + cc+0)*Nn + n]     = a00;
    d_trend_out[(b*PREDn + cc+1)*Nn + n]     = a01;
    d_trend_out[(b*PREDn + cc+0)*Nn + n + 1] = a10;
    d_trend_out[(b*PREDn + cc+1)*Nn + n + 1] = a11;
}

// ---------------- CEM (bt-split, parity recon, packed attn) ----------------
__global__ void __launch_bounds__(256) k_cem(int bt0)
{
    __shared__ float  resv[64];
    __shared__ float2 tw2[64];
    __shared__ float2 Fs[32];
    __shared__ float  aMag[32];
    __shared__ float2 part[8][32];
    __shared__ float2 g2s[32][8];
    __shared__ float  sMaxA;
    int bt = blockIdx.x + bt0;
    int tid = threadIdx.x;

    if (tid < 64) { resv[tid] = d_res[bt*64 + tid]; tw2[tid] = d_TW64[tid]; }
    __syncthreads();

    {
        int m = tid & 31, q = tid >> 5;
        float re = 0.f, im = 0.f;
        int k = (m * (q*8)) & 63;
        #pragma unroll
        for (int j = 0; j < 8; j++) {
            float v = resv[q*8 + j];
            float2 t = tw2[k];
            re = fmaf(v,  t.x, re);
            im = fmaf(v, -t.y, im);
            k = (k + m) & 63;
        }
        part[q][m] = make_float2(re, im);
    }
    __syncthreads();
    if (tid < 32) {
        float re = 0.f, im = 0.f;
        #pragma unroll
        for (int q = 0; q < 8; q++) { float2 p = part[q][tid]; re += p.x; im += p.y; }
        Fs[tid] = make_float2(re, im);
        float mag = sqrtf(re*re + im*im);
        aMag[tid] = mag;
        #pragma unroll
        for (int o = 16; o; o >>= 1) mag = fmaxf(mag, __shfl_xor_sync(0xffffffffu, mag, o));
        if (tid == 0) sMaxA = mag;
    }
    __syncthreads();

    {
        int h = tid >> 5, m = tid & 31;
        float scale = aMag[m] * d_cabs[h] * 0.25f;
        float mA = sMaxA;
        float denom = 0.f;
        ull gp = 0ull;
        const ull* Fu = (const ull*)Fs;
        #pragma unroll 4
        for (int n = 0; n < 32; n++) {
            float p = __expf(scale * (aMag[n] - mA));
            denom += p;
            gp = ffma2(Fu[n], pack2(p, p), gp);
        }
        float sc = (m == 0 ? 1.f : 2.f) / (64.f * denom);
        float2 g = unpack2(gp);
        g2s[m][h] = make_float2(g.x * sc, -g.y * sc);
    }
    __syncthreads();

    // recon with parity trick: out(nb) = g0 + E + O ; out(nb+32) = g0 + E - O
    {
        int h = tid & 7, nb = tid >> 3;
        float g0 = g2s[0][h].x;
        float accE = 0.f, accO = 0.f;
        int k = 0;
        #pragma unroll
        for (int m = 1; m < 32; m++) {
            k = (k + nb) & 63;
            float2 g  = g2s[m][h];
            float2 tw = tw2[k];
            float sm = fmaf(g.x, tw.x, g.y * tw.y);
            if (m & 1) accO += sm; else accE += sm;
        }
        d_G2[bt*512 + nb*8 + h]      = g0 + accE + accO;
        d_G2[bt*512 + (nb+32)*8 + h] = (g0 + accE) - accO;
    }
}

// ---------------- fused TEM (b-split): rfft + attention -> d_z ----------------
__global__ void __launch_bounds__(256) k_tem(int b0)
{
    __shared__ __align__(16) ull sd[256*8];
    __shared__ ull twp[512];
    __shared__ float Csh[8][8][8];
    __shared__ float Osh[8][8];

    ull* Hre_pk = sd;                 // [32][8]
    ull* Him_pk = sd + 256;           // [32][8]
    ull* zpk    = sd + 512;           // [8][66]
    float* fHre = (float*)Hre_pk;
    float* fHim = (float*)Him_pk;

    int n = blockIdx.x, b = blockIdx.y + b0;
    int tid = threadIdx.x;

    for (int i = tid; i < 512; i += 256) twp[i] = d_TWp[i];
    for (int i = tid; i < 512; i += 256) ((float*)Csh)[i] = ((const float*)d_C)[i];
    if (tid < 64) ((float*)Osh)[tid] = ((const float*)d_Otil)[tid];

    {
        int t = tid;
        int tb = (t == 0) ? 256 : 512 - t;
        const float* ga = &d_G2[(b*512 + t )*512 + n*8];
        const float* gb = &d_G2[(b*512 + tb)*512 + n*8];
        float4 a0 = *(const float4*)ga,     a1 = *(const float4*)(ga + 4);
        float4 b0v = *(const float4*)gb,    b1v = *(const float4*)(gb + 4);
        ull* dst = &sd[t*8];
        if (t == 0) {
            dst[0] = pack2(a0.x, b0v.x); dst[1] = pack2(a0.y, b0v.y);
            dst[2] = pack2(a0.z, b0v.z); dst[3] = pack2(a0.w, b0v.w);
            dst[4] = pack2(a1.x, b1v.x); dst[5] = pack2(a1.y, b1v.y);
            dst[6] = pack2(a1.z, b1v.z); dst[7] = pack2(a1.w, b1v.w);
        } else {
            dst[0] = pack2(a0.x + b0v.x, a0.x - b0v.x);
            dst[1] = pack2(a0.y + b0v.y, a0.y - b0v.y);
            dst[2] = pack2(a0.z + b0v.z, a0.z - b0v.z);
            dst[3] = pack2(a0.w + b0v.w, a0.w - b0v.w);
            dst[4] = pack2(a1.x + b1v.x, a1.x - b1v.x);
            dst[5] = pack2(a1.y + b1v.y, a1.y - b1v.y);
            dst[6] = pack2(a1.z + b1v.z, a1.z - b1v.z);
            dst[7] = pack2(a1.w + b1v.w, a1.w - b1v.w);
        }
    }
    __syncthreads();

    int tau = tid >> 2, cg = (tid & 3) * 2;
    ull acc0, acc1;
    {
        float sgn = (tau & 1) ? -1.f : 1.f;
        float2 s0 = unpack2(sd[cg]);
        float2 s1 = unpack2(sd[cg + 1]);
        acc0 = pack2(fmaf(sgn, s0.y, s0.x), 0.f);
        acc1 = pack2(fmaf(sgn, s1.y, s1.x), 0.f);
    }
    {
        int k = tau;
        #pragma unroll 4
        for (int t = 1; t < 256; t++) {
            ull w = twp[k];
            ulonglong2 p = *(const ulonglong2*)&sd[t*8 + cg];
            acc0 = ffma2(p.x, w, acc0);
            acc1 = ffma2(p.y, w, acc1);
            k = (k + tau) & 511;
        }
    }
    __syncthreads();

    {
        int base = (tau >> 1) * 16 + (tau & 1);
        float2 v0 = unpack2(acc0);
        float2 v1 = unpack2(acc1);
        fHre[base + cg*2]       = v0.x;
        fHim[base + cg*2]       = v0.y;
        fHre[base + (cg+1)*2]   = v1.x;
        fHim[base + (cg+1)*2]   = v1.y;
    }
    __syncthreads();

    {
        int npq = tid >> 3, hp = tid & 7;
        const ulonglong2* hr = (const ulonglong2*)(Hre_pk + npq*8);
        const ulonglong2* hi = (const ulonglong2*)(Him_pk + npq*8);
        ull zr2 = 0ull, zi2 = 0ull;
        #pragma unroll
        for (int q = 0; q < 4; q++) {
            ulonglong2 r = hr[q], im = hi[q];
            float o0 = Osh[hp][2*q], o1 = Osh[hp][2*q+1];
            zr2 = ffma2(r.x,  pack2(o0, o0), zr2);
            zr2 = ffma2(r.y,  pack2(o1, o1), zr2);
            zi2 = ffma2(im.x, pack2(o0, o0), zi2);
            zi2 = ffma2(im.y, pack2(o1, o1), zi2);
        }
        float2 zr = unpack2(zr2), zi = unpack2(zi2);
        zpk[hp*66 + 2*npq]     = pack2(zr.x, zi.x);
        zpk[hp*66 + 2*npq + 1] = pack2(zr.y, zi.y);
    }
    __syncthreads();

    int mq = tid >> 3, hp = tid & 7;
    #pragma unroll
    for (int mi = 0; mi < 2; mi++) {
        int m = mq + mi*32;
        float uR[8], uI[8];
        #pragma unroll
        for (int h2 = 0; h2 < 8; h2++) { uR[h2] = 0.f; uI[h2] = 0.f; }
        {
            int base = (m >> 1) * 16 + (m & 1);
            #pragma unroll
            for (int h1 = 0; h1 < 8; h1++) {
                float hr = fHre[base + h1*2];
                float hi = fHim[base + h1*2];
                #pragma unroll
                for (int h2 = 0; h2 < 8; h2++) {
                    float c = Csh[hp][h1][h2];
                    uR[h2] = fmaf(hr, c, uR[h2]);
                    uI[h2] = fmaf(hi, c, uI[h2]);
                }
            }
        }
        ull uR2[8], uI2[8];
        #pragma unroll
        for (int h2 = 0; h2 < 8; h2++) {
            uR2[h2] = pack2(uR[h2], uR[h2]);
            uI2[h2] = pack2(uI[h2], uI[h2]);
        }

        float mrun = -1e30f, lrun = 0.f;
        ull az = 0ull;

        #pragma unroll 2
        for (int ch = 0; ch < 8; ch++) {
            float s[8];
            ulonglong2 zc[4];
            #pragma unroll
            for (int j = 0; j < 4; j++) {
                int npq = ch*4 + j;
                const ulonglong2* hr = (const ulonglong2*)(Hre_pk + npq*8);
                const ulonglong2* hi = (const ulonglong2*)(Him_pk + npq*8);
                ull A = 0ull, B = 0ull, Cc = 0ull, D = 0ull;
                #pragma unroll
                for (int q = 0; q < 4; q++) {
                    ulonglong2 r = hr[q], im = hi[q];
                    A  = ffma2(r.x,  uR2[2*q],   A);
                    A  = ffma2(r.y,  uR2[2*q+1], A);
                    B  = ffma2(im.x, uI2[2*q],   B);
                    B  = ffma2(im.y, uI2[2*q+1], B);
                    Cc = ffma2(r.x,  uI2[2*q],   Cc);
                    Cc = ffma2(r.y,  uI2[2*q+1], Cc);
                    D  = ffma2(im.x, uR2[2*q],   D);
                    D  = ffma2(im.y, uR2[2*q+1], D);
                }
                float2 a = unpack2(A), bb = unpack2(B), c = unpack2(Cc), d = unpack2(D);
                float sr0 = a.x + bb.x, si0 = d.x - c.x;
                float sr1 = a.y + bb.y, si1 = d.y - c.y;
                s[2*j+0] = sqrtf(fmaf(sr0, sr0, si0*si0)) * 0.25f;
                s[2*j+1] = sqrtf(fmaf(sr1, sr1, si1*si1)) * 0.25f;
                zc[j] = *(const ulonglong2*)&zpk[hp*66 + 2*npq];
            }
            float cmax = s[0];
            #pragma unroll
            for (int j = 1; j < 8; j++) cmax = fmaxf(cmax, s[j]);
            float mnew = fmaxf(mrun, cmax);
            float corr = __expf(mrun - mnew);
            float psum = 0.f;
            ull pz = 0ull;
            #pragma unroll
            for (int j = 0; j < 4; j++) {
                float p0 = __expf(s[2*j+0] - mnew);
                float p1 = __expf(s[2*j+1] - mnew);
                psum += p0 + p1;
                pz = ffma2(zc[j].x, pack2(p0, p0), pz);
                pz = ffma2(zc[j].y, pack2(p1, p1), pz);
            }
            lrun = fmaf(lrun, corr, psum);
            az = ffma2(az, pack2(corr, corr), pz);
            mrun = mnew;
        }
        float inv = 1.f / lrun;
        float2 a = unpack2(az);
        float ar = a.x * inv, ai = a.y * inv;
        #pragma unroll
        for (int off = 4; off >= 1; off >>= 1) {
            ar += __shfl_down_sync(0xffffffffu, ar, off, 8);
            ai += __shfl_down_sync(0xffffffffu, ai, off, 8);
        }
        if (hp == 0) d_z[(b*64 + n)*64 + m] = make_float2(ar, ai);
    }
}

// ---------------- fuse ----------------
__global__ void k_fuse(const float* __restrict__ dr_b, const float* __restrict__ out_b,
                       const float* __restrict__ wf, float* __restrict__ out)
{
    __shared__ float zr[64], zi[64];
    int bn = blockIdx.x;
    int b = bn >> 6, n = bn & 63;
    int tid = threadIdx.x; // 96
    if (tid < 64) {
        float2 v = d_z[bn*64 + tid];
        zr[tid] = v.x; zi[tid] = v.y;
    }
    __syncthreads();
    float acc = zr[0] * d_Cw[tid];
    #pragma unroll 4
    for (int tau = 1; tau < 64; tau++) {
        acc = fmaf( 2.f*zr[tau], d_Cw[tau*PREDn + tid], acc);
        acc = fmaf(-2.f*zi[tau], d_Sw[tau*PREDn + tid], acc);
    }
    float xo = acc * (1.f/512.f) + dr_b[0]*d_Cw[tid] + out_b[tid];
    float v  = wf[0]*xo + wf[1]*d_trend_out[(b*PREDn + tid)*Nn + n];
    out[(b*PREDn + tid)*Nn + n] = v;
}

// ---------------- stream/event context ----------------
namespace {
struct GpuCtx {
    cudaStream_t s1 = nullptr, s2 = nullptr;
    cudaEvent_t eFork = nullptr, eResA = nullptr, eResB = nullptr, eMLP = nullptr;
    cudaEvent_t eCW = nullptr, eCemA = nullptr, eTemA = nullptr;
    bool ok = false;
    GpuCtx() {
        ok = (cudaStreamCreateWithFlags(&s1, cudaStreamNonBlocking) == cudaSuccess) &&
             (cudaStreamCreateWithFlags(&s2, cudaStreamNonBlocking) == cudaSuccess) &&
             (cudaEventCreateWithFlags(&eFork, cudaEventDisableTiming) == cudaSuccess) &&
             (cudaEventCreateWithFlags(&eResA, cudaEventDisableTiming) == cudaSuccess) &&
             (cudaEventCreateWithFlags(&eResB, cudaEventDisableTiming) == cudaSuccess) &&
             (cudaEventCreateWithFlags(&eMLP,  cudaEventDisableTiming) == cudaSuccess) &&
             (cudaEventCreateWithFlags(&eCW,   cudaEventDisableTiming) == cudaSuccess) &&
             (cudaEventCreateWithFlags(&eCemA, cudaEventDisableTiming) == cudaSuccess) &&
             (cudaEventCreateWithFlags(&eTemA, cudaEventDisableTiming) == cudaSuccess);
    }
};
GpuCtx g_ctx;
}

// ---------------- launch ----------------
// NOTE capture rule: every cudaStreamWaitEvent must be enqueued AFTER the
// matching cudaEventRecord in host order. s2's temA is therefore enqueued
// late, after eCemA is recorded on the default stream.
extern "C" void kernel_launch(void* const* d_in, const int* in_sizes, int n_in,
                              void* d_out, int out_size)
{
    const float* x      = (const float*)d_in[0];
    const float* emb    = (const float*)d_in[1];
    const float* dec_w  = (const float*)d_in[2];
    const float* dec_b  = (const float*)d_in[3];
    const float* mlp_w1 = (const float*)d_in[4];
    const float* mlp_b1 = (const float*)d_in[5];
    const float* mlp_w2 = (const float*)d_in[6];
    const float* mlp_b2 = (const float*)d_in[7];
    const float* mlp_w3 = (const float*)d_in[8];
    const float* mlp_b3 = (const float*)d_in[9];
    const float* cWq    = (const float*)d_in[10];
    const float* cWk    = (const float*)d_in[11];
    const float* cWv    = (const float*)d_in[12];
    const float* cWo    = (const float*)d_in[13];
    const float* tWq    = (const float*)d_in[14];
    const float* tWk    = (const float*)d_in[15];
    const float* tWv    = (const float*)d_in[16];
    const float* tWo    = (const float*)d_in[17];
    const float* dr_w   = (const float*)d_in[18];
    const float* dr_b   = (const float*)d_in[19];
    const float* out_w  = (const float*)d_in[20];
    const float* out_b  = (const float*)d_in[21];
    const float* W_fuse = (const float*)d_in[22];
    float* out = (float*)d_out;

    if (g_ctx.ok) {
        cudaEventRecord(g_ctx.eFork, 0);
        cudaStreamWaitEvent(g_ctx.s1, g_ctx.eFork, 0);
        cudaStreamWaitEvent(g_ctx.s2, g_ctx.eFork, 0);

        // s1: trend branch, decomp split by b-halves
        k_decomp<<<dim3(16, 4), 512, 0, g_ctx.s1>>>(x, dec_w, dec_b, 0);
        cudaEventRecord(g_ctx.eResA, g_ctx.s1);
        k_decomp<<<dim3(16, 4), 512, 0, g_ctx.s1>>>(x, dec_w, dec_b, 4);
        cudaEventRecord(g_ctx.eResB, g_ctx.s1);
        k_gemm1<<<dim3(8, 16), 256, 0, g_ctx.s1>>>(mlp_w1, mlp_b1);
        k_gemm2<<<dim3(8, 16), 256, 0, g_ctx.s1>>>(mlp_w2, mlp_b2);
        k_gemm3<<<dim3(3, 16), 256, 0, g_ctx.s1>>>(mlp_w3, mlp_b3);
        cudaEventRecord(g_ctx.eMLP, g_ctx.s1);

        // s2 segment 1: tem params + cwsw (in-order on s2)
        k_setupB<<<1, 1024, 0, g_ctx.s2>>>(emb, cWv, cWo, tWq, tWk, tWv, tWo, dr_w);
        k_setup_cwsw<<<64, 96, 0, g_ctx.s2>>>(out_w);
        cudaEventRecord(g_ctx.eCW, g_ctx.s2);

        // s0: setupA -> cemA (record) -> cemB
        k_setupA<<<1, 512>>>(emb, cWq, cWk);
        cudaStreamWaitEvent(0, g_ctx.eResA, 0);
        k_cem<<<2048, 256>>>(0);
        cudaEventRecord(g_ctx.eCemA, 0);
        cudaStreamWaitEvent(0, g_ctx.eResB, 0);
        k_cem<<<2048, 256>>>(2048);

        // s2 segment 2: temA waits on cemA (record already enqueued above);
        // setupB ordering is implicit (same stream).
        cudaStreamWaitEvent(g_ctx.s2, g_ctx.eCemA, 0);
        k_tem<<<dim3(64, 4), 256, 0, g_ctx.s2>>>(0);
        cudaEventRecord(g_ctx.eTemA, g_ctx.s2);

        // s0: temB (after cemB in-order; needs setupB -> use eCW which follows it on s2)
        cudaStreamWaitEvent(0, g_ctx.eCW, 0);
        k_tem<<<dim3(64, 4), 256>>>(4);
        cudaStreamWaitEvent(0, g_ctx.eTemA, 0);
        cudaStreamWaitEvent(0, g_ctx.eMLP, 0);
        k_fuse<<<Bn*Nn, 96>>>(dr_b, out_b, W_fuse, out);
    } else {
        k_setupA<<<1, 512>>>(emb, cWq, cWk);
        k_setupB<<<1, 1024>>>(emb, cWv, cWo, tWq, tWk, tWv, tWo, dr_w);
        k_setup_cwsw<<<64, 96>>>(out_w);
        k_decomp<<<dim3(16, 8), 512>>>(x, dec_w, dec_b, 0);
        k_gemm1<<<dim3(8, 16), 256>>>(mlp_w1, mlp_b1);
        k_gemm2<<<dim3(8, 16), 256>>>(mlp_w2, mlp_b2);
        k_gemm3<<<dim3(3, 16), 256>>>(mlp_w3, mlp_b3);
        k_cem<<<4096, 256>>>(0);
        k_tem<<<dim3(64, 8), 256>>>(0);
        k_fuse<<<Bn*Nn, 96>>>(dr_b, out_b, W_fuse, out);
    }
}

// round 10
// speedup vs baseline: 1.1876x; 1.1876x over previous
#include <cuda_runtime.h>
#include <math.h>

#define Bn 8
#define Tn 512
#define Nn 64
#define Hn 8
#define Mt 64
#define PREDn 96
#define HIDn 256

#define TWO_PI 6.283185307179586
typedef unsigned long long ull;

// ---------------- f32x2 helpers ----------------
__device__ __forceinline__ ull ffma2(ull a, ull b, ull c) {
    ull d;
    asm("fma.rn.f32x2 %0, %1, %2, %3;" : "=l"(d) : "l"(a), "l"(b), "l"(c));
    return d;
}
__device__ __forceinline__ ull pack2(float x, float y) {
    ull r;
    asm("mov.b64 %0, {%1, %2};" : "=l"(r) : "f"(x), "f"(y));
    return r;
}
__device__ __forceinline__ float2 unpack2(ull v) {
    float2 r;
    asm("mov.b64 {%0, %1}, %2;" : "=f"(r.x), "=f"(r.y) : "l"(v));
    return r;
}

// ---------------- device scratch ----------------
__device__ float  d_res[Bn*Tn*Nn];
__device__ float  d_trend[Bn*Tn*Nn];
__device__ float  d_h1[512*256];
__device__ float  d_h2[512*256];
__device__ float  d_trend_out[Bn*PREDn*Nn];
__device__ float  d_G2[Bn*Tn*Nn*Hn];       // (b,t,(n,h))
__device__ float2 d_z[Bn*Nn*Mt];           // (b,n,tau)

// precomputed small params
__device__ float  d_cabs[Hn];
__device__ float  d_C[Hn][Hn][Hn];
__device__ float  d_Otil[Hn][Hn];
__device__ float2 d_TW64[64];
__device__ ull    d_TWp[512];
__device__ float  d_Cw[Mt*PREDn], d_Sw[Mt*PREDn];

// ---------------- setupA: twiddles + cabs ----------------
__global__ void k_setupA(const float* __restrict__ emb,
                         const float* __restrict__ cWq, const float* __restrict__ cWk)
{
    __shared__ float eq[128], ek[128];
    int t = threadIdx.x; // 512 threads

    if (t < 64) {
        double a = TWO_PI * (double)t / 64.0;
        d_TW64[t] = make_float2((float)cos(a), (float)sin(a));
    }
    {
        double a = TWO_PI * (double)t / 512.0;
        d_TWp[t] = pack2((float)cos(a), -(float)sin(a));
    }
    if (t < 128) {
        float aq = 0.f, ak = 0.f;
        #pragma unroll 4
        for (int d = 0; d < 128; d++) {
            float e = emb[d];
            aq = fmaf(e, cWq[d*128 + t], aq);
            ak = fmaf(e, cWk[d*128 + t], ak);
        }
        eq[t] = aq; ek[t] = ak;
    }
    __syncthreads();
    if (t < 8) {
        float c = 0.f;
        #pragma unroll
        for (int d = 0; d < 16; d++) c = fmaf(eq[t*16 + d], ek[t*16 + d], c);
        d_cabs[t] = fabsf(c);
    }
}

// ---------------- setupB: C / Otil ----------------
__global__ void k_setupB(const float* __restrict__ emb,
                         const float* __restrict__ cWv, const float* __restrict__ cWo,
                         const float* __restrict__ tWq, const float* __restrict__ tWk,
                         const float* __restrict__ tWv, const float* __restrict__ tWo,
                         const float* __restrict__ dr_w)
{
    __shared__ float ev[128], wod[128];
    __shared__ float P[8][128];
    __shared__ float Qg[8][128], Kg[8][128], Vg[8][128];
    int t = threadIdx.x; // 1024 threads

    if (t < 128) {
        float av = 0.f;
        #pragma unroll 4
        for (int d = 0; d < 128; d++) av = fmaf(emb[d], cWv[d*128 + t], av);
        ev[t] = av;
        float s = 0.f;
        #pragma unroll 4
        for (int e = 0; e < 128; e++) s = fmaf(tWo[t*128 + e], dr_w[e], s);
        wod[t] = s;
    }
    __syncthreads();

    {
        int h = t >> 7, e = t & 127;
        float s = 0.f;
        #pragma unroll
        for (int d = 0; d < 16; d++) s = fmaf(ev[h*16 + d], cWo[(h*16 + d)*128 + e], s);
        P[h][e] = s;
    }
    __syncthreads();

    {
        int h = t >> 7, e = t & 127;
        float sq = 0.f, sk = 0.f, sv = 0.f;
        #pragma unroll 4
        for (int d = 0; d < 128; d++) {
            float p = P[h][d];
            sq = fmaf(p, tWq[d*128 + e], sq);
            sk = fmaf(p, tWk[d*128 + e], sk);
            sv = fmaf(p, tWv[d*128 + e], sv);
        }
        Qg[h][e] = sq; Kg[h][e] = sk; Vg[h][e] = sv;
    }
    __syncthreads();

    if (t < 512) {
        int hp = t >> 6, h1 = (t >> 3) & 7, h2 = t & 7;
        float s = 0.f;
        #pragma unroll
        for (int d = 0; d < 16; d++) s = fmaf(Qg[h1][hp*16 + d], Kg[h2][hp*16 + d], s);
        d_C[hp][h1][h2] = s;
    }
    if (t >= 512 && t < 576) {
        int u = t - 512;
        int hp = u >> 3, h2 = u & 7;
        float s = 0.f;
        #pragma unroll
        for (int d = 0; d < 16; d++) s = fmaf(Vg[h2][hp*16 + d], wod[hp*16 + d], s);
        d_Otil[hp][h2] = s;
    }
}

// ---------------- cwsw: self-contained, off critical path ----------------
__global__ void k_setup_cwsw(const float* __restrict__ out_w)
{
    int tau = blockIdx.x, p = threadIdx.x; // 64 x 96
    float c = 0.f, s = 0.f;
    int k = 0;
    #pragma unroll 4
    for (int t = 0; t < 512; t++) {
        float w = out_w[t*PREDn + p];
        float cs, sn;
        sincospif((float)k * (1.f/256.f), &sn, &cs);
        c = fmaf(cs, w, c);
        s = fmaf(sn, w, s);
        k = (k + tau) & 511;
    }
    d_Cw[tau*PREDn + p] = c;
    d_Sw[tau*PREDn + p] = s;
}

// ---------------- decomposition ----------------
__global__ void k_decomp(const float* __restrict__ x,
                         const float* __restrict__ dec_w, const float* __restrict__ dec_b)
{
    __shared__ float xs[80][64];
    int b = blockIdx.y, t0 = blockIdx.x * 32;
    int tid = threadIdx.x;
    const float* xb = x + b*Tn*Nn;

    for (int i = tid; i < 80*64; i += 512) {
        int row = i >> 6, col = i & 63;
        int tg = t0 - 24 + row;
        tg = tg < 0 ? 0 : (tg > 511 ? 511 : tg);
        xs[row][col] = xb[tg*64 + col];
    }
    __syncthreads();

    float w0 = dec_w[0], w1v = dec_w[1], bb0 = dec_b[0], bb1 = dec_b[1];
    int c = tid >> 6, n = tid & 63;
    int r0 = c * 4;
    float s49 = 0.f, s17 = 0.f;
    #pragma unroll
    for (int j = 0; j < 49; j++) {
        float v = xs[r0 + j][n];
        s49 += v;
        if (j >= 16 && j <= 32) s17 += v;
    }
    #pragma unroll
    for (int s = 0; s < 4; s++) {
        if (s > 0) {
            s49 += xs[r0 + 48 + s][n] - xs[r0 + s - 1][n];
            s17 += xs[r0 + 32 + s][n] - xs[r0 + 15 + s][n];
        }
        float xv = xs[r0 + 24 + s][n];
        float m17 = s17 * (1.f/17.f), m49 = s49 * (1.f/49.f);
        float l0 = fmaf(xv, w0, bb0);
        float l1 = fmaf(xv, w1v, bb1);
        float mx = fmaxf(l0, l1);
        float e0 = __expf(l0 - mx), e1 = __expf(l1 - mx);
        float tr = (m17*e0 + m49*e1) / (e0 + e1);
        int gi = b*Tn*Nn + (t0 + r0 + s)*64 + n;
        d_trend[gi] = tr;
        d_res[gi]   = xv - tr;
    }
}

// ---------------- MLP GEMMs (proven) ----------------
__global__ void k_gemm1(const float* __restrict__ w1, const float* __restrict__ b1)
{
    __shared__ float As[32][36];
    __shared__ float Ws[32][36];
    int r0 = blockIdx.y * 32, c0 = blockIdx.x * 32;
    int b = r0 >> 6, n0 = r0 & 32;
    int tid = threadIdx.x;
    int lr = tid >> 3, l4 = (tid & 7) * 4;
    int ty = tid >> 4, cy = tid & 15;

    float2 bias = *(const float2*)&b1[c0 + 2*cy];
    float a00 = bias.x, a01 = bias.y, a10 = bias.x, a11 = bias.y;

    float4 ra = *(const float4*)&d_trend[b*32768 + lr*64 + n0 + l4];
    float4 rw = *(const float4*)&w1[lr*256 + c0 + l4];

    for (int kt = 0; kt < 16; kt++) {
        *(float4*)&As[lr][l4] = ra;
        *(float4*)&Ws[lr][l4] = rw;
        __syncthreads();
        if (kt < 15) {
            int kg = (kt+1)*32 + lr;
            ra = *(const float4*)&d_trend[b*32768 + kg*64 + n0 + l4];
            rw = *(const float4*)&w1[kg*256 + c0 + l4];
        }
        #pragma unroll
        for (int k = 0; k < 32; k++) {
            float2 a = *(const float2*)&As[k][2*ty];
            float2 w = *(const float2*)&Ws[k][2*cy];
            a00 = fmaf(a.x, w.x, a00); a01 = fmaf(a.x, w.y, a01);
            a10 = fmaf(a.y, w.x, a10); a11 = fmaf(a.y, w.y, a11);
        }
        __syncthreads();
    }
    int r = r0 + 2*ty, cc = c0 + 2*cy;
    d_h1[(r+0)*256 + cc+0] = fmaxf(a00, 0.f);
    d_h1[(r+0)*256 + cc+1] = fmaxf(a01, 0.f);
    d_h1[(r+1)*256 + cc+0] = fmaxf(a10, 0.f);
    d_h1[(r+1)*256 + cc+1] = fmaxf(a11, 0.f);
}

__global__ void k_gemm2(const float* __restrict__ w2, const float* __restrict__ b2)
{
    __shared__ float As[32][34];
    __shared__ float Ws[32][36];
    int r0 = blockIdx.y * 32, c0 = blockIdx.x * 32;
    int tid = threadIdx.x;
    int alr = tid >> 3, al4 = (tid & 7) * 4;
    int ty = tid >> 4, cy = tid & 15;

    float2 bias = *(const float2*)&b2[c0 + 2*cy];
    float a00 = bias.x, a01 = bias.y, a10 = bias.x, a11 = bias.y;

    float4 ra = *(const float4*)&d_h1[(r0 + alr)*256 + al4];
    float4 rw = *(const float4*)&w2[alr*256 + c0 + al4];

    for (int kt = 0; kt < 8; kt++) {
        As[al4+0][alr] = ra.x; As[al4+1][alr] = ra.y;
        As[al4+2][alr] = ra.z; As[al4+3][alr] = ra.w;
        *(float4*)&Ws[alr][al4] = rw;
        __syncthreads();
        if (kt < 7) {
            ra = *(const float4*)&d_h1[(r0 + alr)*256 + (kt+1)*32 + al4];
            rw = *(const float4*)&w2[((kt+1)*32 + alr)*256 + c0 + al4];
        }
        #pragma unroll
        for (int k = 0; k < 32; k++) {
            float2 a = *(const float2*)&As[k][2*ty];
            float2 w = *(const float2*)&Ws[k][2*cy];
            a00 = fmaf(a.x, w.x, a00); a01 = fmaf(a.x, w.y, a01);
            a10 = fmaf(a.y, w.x, a10); a11 = fmaf(a.y, w.y, a11);
        }
        __syncthreads();
    }
    int r = r0 + 2*ty, cc = c0 + 2*cy;
    d_h2[(r+0)*256 + cc+0] = fmaxf(a00, 0.f);
    d_h2[(r+0)*256 + cc+1] = fmaxf(a01, 0.f);
    d_h2[(r+1)*256 + cc+0] = fmaxf(a10, 0.f);
    d_h2[(r+1)*256 + cc+1] = fmaxf(a11, 0.f);
}

__global__ void k_gemm3(const float* __restrict__ w3, const float* __restrict__ b3)
{
    __shared__ float As[32][34];
    __shared__ float Ws[32][36];
    int r0 = blockIdx.y * 32, c0 = blockIdx.x * 32;
    int tid = threadIdx.x;
    int alr = tid >> 3, al4 = (tid & 7) * 4;
    int ty = tid >> 4, cy = tid & 15;

    float2 bias = *(const float2*)&b3[c0 + 2*cy];
    float a00 = bias.x, a01 = bias.y, a10 = bias.x, a11 = bias.y;

    float4 ra = *(const float4*)&d_h2[(r0 + alr)*256 + al4];
    float4 rw = *(const float4*)&w3[alr*96 + c0 + al4];

    for (int kt = 0; kt < 8; kt++) {
        As[al4+0][alr] = ra.x; As[al4+1][alr] = ra.y;
        As[al4+2][alr] = ra.z; As[al4+3][alr] = ra.w;
        *(float4*)&Ws[alr][al4] = rw;
        __syncthreads();
        if (kt < 7) {
            ra = *(const float4*)&d_h2[(r0 + alr)*256 + (kt+1)*32 + al4];
            rw = *(const float4*)&w3[((kt+1)*32 + alr)*96 + c0 + al4];
        }
        #pragma unroll
        for (int k = 0; k < 32; k++) {
            float2 a = *(const float2*)&As[k][2*ty];
            float2 w = *(const float2*)&Ws[k][2*cy];
            a00 = fmaf(a.x, w.x, a00); a01 = fmaf(a.x, w.y, a01);
            a10 = fmaf(a.y, w.x, a10); a11 = fmaf(a.y, w.y, a11);
        }
        __syncthreads();
    }
    int r = r0 + 2*ty, cc = c0 + 2*cy;
    int b = r >> 6, n = r & 63;
    d_trend_out[(b*PREDn + cc+0)*Nn + n]     = a00;
    d_trend_out[(b*PREDn + cc+1)*Nn + n]     = a01;
    d_trend_out[(b*PREDn + cc+0)*Nn + n + 1] = a10;
    d_trend_out[(b*PREDn + cc+1)*Nn + n + 1] = a11;
}

// ---------------- CEM: parity recon + packed attn (R9-verified internals) ----------------
__global__ void __launch_bounds__(256) k_cem()
{
    __shared__ float  resv[64];
    __shared__ float2 tw2[64];
    __shared__ float2 Fs[32];
    __shared__ float  aMag[32];
    __shared__ float2 part[8][32];
    __shared__ float2 g2s[32][8];
    __shared__ float  sMaxA;
    int bt = blockIdx.x;
    int tid = threadIdx.x;

    if (tid < 64) { resv[tid] = d_res[bt*64 + tid]; tw2[tid] = d_TW64[tid]; }
    __syncthreads();

    {
        int m = tid & 31, q = tid >> 5;
        float re = 0.f, im = 0.f;
        int k = (m * (q*8)) & 63;
        #pragma unroll
        for (int j = 0; j < 8; j++) {
            float v = resv[q*8 + j];
            float2 t = tw2[k];
            re = fmaf(v,  t.x, re);
            im = fmaf(v, -t.y, im);
            k = (k + m) & 63;
        }
        part[q][m] = make_float2(re, im);
    }
    __syncthreads();
    if (tid < 32) {
        float re = 0.f, im = 0.f;
        #pragma unroll
        for (int q = 0; q < 8; q++) { float2 p = part[q][tid]; re += p.x; im += p.y; }
        Fs[tid] = make_float2(re, im);
        float mag = sqrtf(re*re + im*im);
        aMag[tid] = mag;
        #pragma unroll
        for (int o = 16; o; o >>= 1) mag = fmaxf(mag, __shfl_xor_sync(0xffffffffu, mag, o));
        if (tid == 0) sMaxA = mag;
    }
    __syncthreads();

    {
        int h = tid >> 5, m = tid & 31;
        float scale = aMag[m] * d_cabs[h] * 0.25f;
        float mA = sMaxA;
        float denom = 0.f;
        ull gp = 0ull;
        const ull* Fu = (const ull*)Fs;
        #pragma unroll 4
        for (int n = 0; n < 32; n++) {
            float p = __expf(scale * (aMag[n] - mA));
            denom += p;
            gp = ffma2(Fu[n], pack2(p, p), gp);
        }
        float sc = (m == 0 ? 1.f : 2.f) / (64.f * denom);
        float2 g = unpack2(gp);
        g2s[m][h] = make_float2(g.x * sc, -g.y * sc);
    }
    __syncthreads();

    // recon with parity trick: out(nb) = g0 + E + O ; out(nb+32) = g0 + E - O
    {
        int h = tid & 7, nb = tid >> 3;
        float g0 = g2s[0][h].x;
        float accE = 0.f, accO = 0.f;
        int k = 0;
        #pragma unroll
        for (int m = 1; m < 32; m++) {
            k = (k + nb) & 63;
            float2 g  = g2s[m][h];
            float2 tw = tw2[k];
            float sm = fmaf(g.x, tw.x, g.y * tw.y);
            if (m & 1) accO += sm; else accE += sm;
        }
        d_G2[bt*512 + nb*8 + h]      = g0 + accE + accO;
        d_G2[bt*512 + (nb+32)*8 + h] = (g0 + accE) - accO;
    }
}

// ---------------- fused TEM: 1 n per block, packed H layout (R7-proven) ----------------
__global__ void __launch_bounds__(256) k_tem()
{
    __shared__ __align__(16) ull sd[256*8];
    __shared__ ull twp[512];
    __shared__ float Csh[8][8][8];
    __shared__ float Osh[8][8];

    ull* Hre_pk = sd;                 // [32][8]
    ull* Him_pk = sd + 256;           // [32][8]
    ull* zpk    = sd + 512;           // [8][66]
    float* fHre = (float*)Hre_pk;
    float* fHim = (float*)Him_pk;

    int n = blockIdx.x, b = blockIdx.y;
    int tid = threadIdx.x;

    for (int i = tid; i < 512; i += 256) twp[i] = d_TWp[i];
    for (int i = tid; i < 512; i += 256) ((float*)Csh)[i] = ((const float*)d_C)[i];
    if (tid < 64) ((float*)Osh)[tid] = ((const float*)d_Otil)[tid];

    {
        int t = tid;
        int tb = (t == 0) ? 256 : 512 - t;
        const float* ga = &d_G2[(b*512 + t )*512 + n*8];
        const float* gb = &d_G2[(b*512 + tb)*512 + n*8];
        float4 a0 = *(const float4*)ga,     a1 = *(const float4*)(ga + 4);
        float4 b0 = *(const float4*)gb,     b1 = *(const float4*)(gb + 4);
        ull* dst = &sd[t*8];
        if (t == 0) {
            dst[0] = pack2(a0.x, b0.x); dst[1] = pack2(a0.y, b0.y);
            dst[2] = pack2(a0.z, b0.z); dst[3] = pack2(a0.w, b0.w);
            dst[4] = pack2(a1.x, b1.x); dst[5] = pack2(a1.y, b1.y);
            dst[6] = pack2(a1.z, b1.z); dst[7] = pack2(a1.w, b1.w);
        } else {
            dst[0] = pack2(a0.x + b0.x, a0.x - b0.x);
            dst[1] = pack2(a0.y + b0.y, a0.y - b0.y);
            dst[2] = pack2(a0.z + b0.z, a0.z - b0.z);
            dst[3] = pack2(a0.w + b0.w, a0.w - b0.w);
            dst[4] = pack2(a1.x + b1.x, a1.x - b1.x);
            dst[5] = pack2(a1.y + b1.y, a1.y - b1.y);
            dst[6] = pack2(a1.z + b1.z, a1.z - b1.z);
            dst[7] = pack2(a1.w + b1.w, a1.w - b1.w);
        }
    }
    __syncthreads();

    int tau = tid >> 2, cg = (tid & 3) * 2;
    ull acc0, acc1;
    {
        float sgn = (tau & 1) ? -1.f : 1.f;
        float2 s0 = unpack2(sd[cg]);
        float2 s1 = unpack2(sd[cg + 1]);
        acc0 = pack2(fmaf(sgn, s0.y, s0.x), 0.f);
        acc1 = pack2(fmaf(sgn, s1.y, s1.x), 0.f);
    }
    {
        int k = tau;
        #pragma unroll 4
        for (int t = 1; t < 256; t++) {
            ull w = twp[k];
            ulonglong2 p = *(const ulonglong2*)&sd[t*8 + cg];
            acc0 = ffma2(p.x, w, acc0);
            acc1 = ffma2(p.y, w, acc1);
            k = (k + tau) & 511;
        }
    }
    __syncthreads();

    {
        int base = (tau >> 1) * 16 + (tau & 1);
        float2 v0 = unpack2(acc0);
        float2 v1 = unpack2(acc1);
        fHre[base + cg*2]       = v0.x;
        fHim[base + cg*2]       = v0.y;
        fHre[base + (cg+1)*2]   = v1.x;
        fHim[base + (cg+1)*2]   = v1.y;
    }
    __syncthreads();

    {
        int npq = tid >> 3, hp = tid & 7;
        const ulonglong2* hr = (const ulonglong2*)(Hre_pk + npq*8);
        const ulonglong2* hi = (const ulonglong2*)(Him_pk + npq*8);
        ull zr2 = 0ull, zi2 = 0ull;
        #pragma unroll
        for (int q = 0; q < 4; q++) {
            ulonglong2 r = hr[q], im = hi[q];
            float o0 = Osh[hp][2*q], o1 = Osh[hp][2*q+1];
            zr2 = ffma2(r.x,  pack2(o0, o0), zr2);
            zr2 = ffma2(r.y,  pack2(o1, o1), zr2);
            zi2 = ffma2(im.x, pack2(o0, o0), zi2);
            zi2 = ffma2(im.y, pack2(o1, o1), zi2);
        }
        float2 zr = unpack2(zr2), zi = unpack2(zi2);
        zpk[hp*66 + 2*npq]     = pack2(zr.x, zi.x);
        zpk[hp*66 + 2*npq + 1] = pack2(zr.y, zi.y);
    }
    __syncthreads();

    int mq = tid >> 3, hp = tid & 7;
    #pragma unroll
    for (int mi = 0; mi < 2; mi++) {
        int m = mq + mi*32;
        float uR[8], uI[8];
        #pragma unroll
        for (int h2 = 0; h2 < 8; h2++) { uR[h2] = 0.f; uI[h2] = 0.f; }
        {
            int base = (m >> 1) * 16 + (m & 1);
            #pragma unroll
            for (int h1 = 0; h1 < 8; h1++) {
                float hr = fHre[base + h1*2];
                float hi = fHim[base + h1*2];
                #pragma unroll
                for (int h2 = 0; h2 < 8; h2++) {
                    float c = Csh[hp][h1][h2];
                    uR[h2] = fmaf(hr, c, uR[h2]);
                    uI[h2] = fmaf(hi, c, uI[h2]);
                }
            }
        }
        ull uR2[8], uI2[8];
        #pragma unroll
        for (int h2 = 0; h2 < 8; h2++) {
            uR2[h2] = pack2(uR[h2], uR[h2]);
            uI2[h2] = pack2(uI[h2], uI[h2]);
        }

        float mrun = -1e30f, lrun = 0.f;
        ull az = 0ull;

        #pragma unroll 2
        for (int ch = 0; ch < 8; ch++) {
            float s[8];
            ulonglong2 zc[4];
            #pragma unroll
            for (int j = 0; j < 4; j++) {
                int npq = ch*4 + j;
                const ulonglong2* hr = (const ulonglong2*)(Hre_pk + npq*8);
                const ulonglong2* hi = (const ulonglong2*)(Him_pk + npq*8);
                ull A = 0ull, B = 0ull, Cc = 0ull, D = 0ull;
                #pragma unroll
                for (int q = 0; q < 4; q++) {
                    ulonglong2 r = hr[q], im = hi[q];
                    A  = ffma2(r.x,  uR2[2*q],   A);
                    A  = ffma2(r.y,  uR2[2*q+1], A);
                    B  = ffma2(im.x, uI2[2*q],   B);
                    B  = ffma2(im.y, uI2[2*q+1], B);
                    Cc = ffma2(r.x,  uI2[2*q],   Cc);
                    Cc = ffma2(r.y,  uI2[2*q+1], Cc);
                    D  = ffma2(im.x, uR2[2*q],   D);
                    D  = ffma2(im.y, uR2[2*q+1], D);
                }
                float2 a = unpack2(A), bb = unpack2(B), c = unpack2(Cc), d = unpack2(D);
                float sr0 = a.x + bb.x, si0 = d.x - c.x;
                float sr1 = a.y + bb.y, si1 = d.y - c.y;
                s[2*j+0] = sqrtf(fmaf(sr0, sr0, si0*si0)) * 0.25f;
                s[2*j+1] = sqrtf(fmaf(sr1, sr1, si1*si1)) * 0.25f;
                zc[j] = *(const ulonglong2*)&zpk[hp*66 + 2*npq];
            }
            float cmax = s[0];
            #pragma unroll
            for (int j = 1; j < 8; j++) cmax = fmaxf(cmax, s[j]);
            float mnew = fmaxf(mrun, cmax);
            float corr = __expf(mrun - mnew);
            float psum = 0.f;
            ull pz = 0ull;
            #pragma unroll
            for (int j = 0; j < 4; j++) {
                float p0 = __expf(s[2*j+0] - mnew);
                float p1 = __expf(s[2*j+1] - mnew);
                psum += p0 + p1;
                pz = ffma2(zc[j].x, pack2(p0, p0), pz);
                pz = ffma2(zc[j].y, pack2(p1, p1), pz);
            }
            lrun = fmaf(lrun, corr, psum);
            az = ffma2(az, pack2(corr, corr), pz);
            mrun = mnew;
        }
        float inv = 1.f / lrun;
        float2 a = unpack2(az);
        float ar = a.x * inv, ai = a.y * inv;
        #pragma unroll
        for (int off = 4; off >= 1; off >>= 1) {
            ar += __shfl_down_sync(0xffffffffu, ar, off, 8);
            ai += __shfl_down_sync(0xffffffffu, ai, off, 8);
        }
        if (hp == 0) d_z[(b*64 + n)*64 + m] = make_float2(ar, ai);
    }
}

// ---------------- fuse ----------------
__global__ void k_fuse(const float* __restrict__ dr_b, const float* __restrict__ out_b,
                       const float* __restrict__ wf, float* __restrict__ out)
{
    __shared__ float zr[64], zi[64];
    int bn = blockIdx.x;
    int b = bn >> 6, n = bn & 63;
    int tid = threadIdx.x; // 96
    if (tid < 64) {
        float2 v = d_z[bn*64 + tid];
        zr[tid] = v.x; zi[tid] = v.y;
    }
    __syncthreads();
    float acc = zr[0] * d_Cw[tid];
    #pragma unroll 4
    for (int tau = 1; tau < 64; tau++) {
        acc = fmaf( 2.f*zr[tau], d_Cw[tau*PREDn + tid], acc);
        acc = fmaf(-2.f*zi[tau], d_Sw[tau*PREDn + tid], acc);
    }
    float xo = acc * (1.f/512.f) + dr_b[0]*d_Cw[tid] + out_b[tid];
    float v  = wf[0]*xo + wf[1]*d_trend_out[(b*PREDn + tid)*Nn + n];
    out[(b*PREDn + tid)*Nn + n] = v;
}

// ---------------- stream/event context ----------------
namespace {
struct GpuCtx {
    cudaStream_t s1 = nullptr, s2 = nullptr;
    cudaEvent_t eFork = nullptr, eRes = nullptr, eMLP = nullptr, eB = nullptr, eCW = nullptr;
    bool ok = false;
    GpuCtx() {
        ok = (cudaStreamCreateWithFlags(&s1, cudaStreamNonBlocking) == cudaSuccess) &&
             (cudaStreamCreateWithFlags(&s2, cudaStreamNonBlocking) == cudaSuccess) &&
             (cudaEventCreateWithFlags(&eFork, cudaEventDisableTiming) == cudaSuccess) &&
             (cudaEventCreateWithFlags(&eRes,  cudaEventDisableTiming) == cudaSuccess) &&
             (cudaEventCreateWithFlags(&eMLP,  cudaEventDisableTiming) == cudaSuccess) &&
             (cudaEventCreateWithFlags(&eB,    cudaEventDisableTiming) == cudaSuccess) &&
             (cudaEventCreateWithFlags(&eCW,   cudaEventDisableTiming) == cudaSuccess);
    }
};
GpuCtx g_ctx;
}

// ---------------- launch (R7 topology) ----------------
extern "C" void kernel_launch(void* const* d_in, const int* in_sizes, int n_in,
                              void* d_out, int out_size)
{
    const float* x      = (const float*)d_in[0];
    const float* emb    = (const float*)d_in[1];
    const float* dec_w  = (const float*)d_in[2];
    const float* dec_b  = (const float*)d_in[3];
    const float* mlp_w1 = (const float*)d_in[4];
    const float* mlp_b1 = (const float*)d_in[5];
    const float* mlp_w2 = (const float*)d_in[6];
    const float* mlp_b2 = (const float*)d_in[7];
    const float* mlp_w3 = (const float*)d_in[8];
    const float* mlp_b3 = (const float*)d_in[9];
    const float* cWq    = (const float*)d_in[10];
    const float* cWk    = (const float*)d_in[11];
    const float* cWv    = (const float*)d_in[12];
    const float* cWo    = (const float*)d_in[13];
    const float* tWq    = (const float*)d_in[14];
    const float* tWk    = (const float*)d_in[15];
    const float* tWv    = (const float*)d_in[16];
    const float* tWo    = (const float*)d_in[17];
    const float* dr_w   = (const float*)d_in[18];
    const float* dr_b   = (const float*)d_in[19];
    const float* out_w  = (const float*)d_in[20];
    const float* out_b  = (const float*)d_in[21];
    const float* W_fuse = (const float*)d_in[22];
    float* out = (float*)d_out;

    if (g_ctx.ok) {
        cudaEventRecord(g_ctx.eFork, 0);
        cudaStreamWaitEvent(g_ctx.s1, g_ctx.eFork, 0);
        cudaStreamWaitEvent(g_ctx.s2, g_ctx.eFork, 0);

        // s1: trend branch
        k_decomp<<<dim3(16, 8), 512, 0, g_ctx.s1>>>(x, dec_w, dec_b);
        cudaEventRecord(g_ctx.eRes, g_ctx.s1);
        k_gemm1<<<dim3(8, 16), 256, 0, g_ctx.s1>>>(mlp_w1, mlp_b1);
        k_gemm2<<<dim3(8, 16), 256, 0, g_ctx.s1>>>(mlp_w2, mlp_b2);
        k_gemm3<<<dim3(3, 16), 256, 0, g_ctx.s1>>>(mlp_w3, mlp_b3);
        cudaEventRecord(g_ctx.eMLP, g_ctx.s1);

        // s2: tem params + cwsw (off critical path)
        k_setupB<<<1, 1024, 0, g_ctx.s2>>>(emb, cWv, cWo, tWq, tWk, tWv, tWo, dr_w);
        cudaEventRecord(g_ctx.eB, g_ctx.s2);
        k_setup_cwsw<<<64, 96, 0, g_ctx.s2>>>(out_w);
        cudaEventRecord(g_ctx.eCW, g_ctx.s2);

        // s0: setupA -> cem -> tem -> fuse
        k_setupA<<<1, 512>>>(emb, cWq, cWk);
        cudaStreamWaitEvent(0, g_ctx.eRes, 0);
        k_cem<<<Bn*Tn, 256>>>();
        cudaStreamWaitEvent(0, g_ctx.eB, 0);
        k_tem<<<dim3(64, 8), 256>>>();
        cudaStreamWaitEvent(0, g_ctx.eMLP, 0);
        cudaStreamWaitEvent(0, g_ctx.eCW, 0);
        k_fuse<<<Bn*Nn, 96>>>(dr_b, out_b, W_fuse, out);
    } else {
        k_setupA<<<1, 512>>>(emb, cWq, cWk);
        k_setupB<<<1, 1024>>>(emb, cWv, cWo, tWq, tWk, tWv, tWo, dr_w);
        k_setup_cwsw<<<64, 96>>>(out_w);
        k_decomp<<<dim3(16, 8), 512>>>(x, dec_w, dec_b);
        k_gemm1<<<dim3(8, 16), 256>>>(mlp_w1, mlp_b1);
        k_gemm2<<<dim3(8, 16), 256>>>(mlp_w2, mlp_b2);
        k_gemm3<<<dim3(3, 16), 256>>>(mlp_w3, mlp_b3);
        k_cem<<<Bn*Tn, 256>>>();
        k_tem<<<dim3(64, 8), 256>>>();
        k_fuse<<<Bn*Nn, 96>>>(dr_b, out_b, W_fuse, out);
    }
}